// round 15
// baseline (speedup 1.0000x reference)
#include <cuda_runtime.h>
#include <cuda_fp16.h>
#include <math.h>
#include <stdint.h>

#define N_LEVELS 16
#define HASH_MASK 32767u
#define HASHMAP_SIZE 32768
#define PTS_PER_CTA 13568      // 148 ranges * 16 levels = 2368 CTAs = 16 waves
#define CTA_THREADS 1024
#define MAX_POINTS 2000000
#define MAX_RANGES 256

#define TP_PTS 1024
#define TP_STRIDE 17           // half2 units; odd -> conflict-free STS

struct ResArr { int r[N_LEVELS]; };

// level-major half2 scratch (carrying the 2^14 prescale): 128 MB
__device__ __align__(256) __half2 g_scr[(size_t)MAX_POINTS * N_LEVELS];
// per-range arrival counters (zero-init; self-resetting each launch)
__device__ int g_cnt[MAX_RANGES];

__device__ __forceinline__ __half2 enc_point(float x, float y, float z, float t,
                                             float rf, const __half2* __restrict__ s_tbl)
{
    const uint32_t P1 = 2654435761u, P2 = 805459861u, P3 = 3674653429u;

    float sx = x * rf, sy = y * rf, sz = z * rf, st = t * rf;
    float gxf = floorf(sx), gyf = floorf(sy), gzf = floorf(sz), gtf = floorf(st);
    float fx = sx - gxf, fy = sy - gyf, fz = sz - gzf, ft = st - gtf;

    uint32_t gx = (uint32_t)(int)gxf;
    uint32_t gy = (uint32_t)(int)gyf;
    uint32_t gz = (uint32_t)(int)gzf;
    uint32_t gt = (uint32_t)(int)gtf;

    uint32_t tx0 = gx,      tx1 = gx + 1u;
    uint32_t ty0 = gy * P1, ty1 = ty0 + P1;
    uint32_t tz0 = gz * P2, tz1 = tz0 + P2;
    uint32_t tt0 = gt * P3, tt1 = tt0 + P3;

    uint32_t hxy[4], hzt[4];
    hxy[0] = tx0 ^ ty0; hxy[1] = tx1 ^ ty0;
    hxy[2] = tx0 ^ ty1; hxy[3] = tx1 ^ ty1;
    hzt[0] = tz0 ^ tt0; hzt[1] = tz1 ^ tt0;
    hzt[2] = tz0 ^ tt1; hzt[3] = tz1 ^ tt1;

    float ux = 1.0f - fx, uy = 1.0f - fy, uz = 1.0f - fz, ut = 1.0f - ft;
    float wxy[4], wzt[4];
    wxy[0] = ux * uy; wxy[1] = fx * uy; wxy[2] = ux * fy; wxy[3] = fx * fy;
    wzt[0] = uz * ut; wzt[1] = fz * ut; wzt[2] = uz * ft; wzt[3] = fz * ft;

    float a0 = 0.0f, a1 = 0.0f;
#pragma unroll
    for (int j = 0; j < 4; ++j) {
#pragma unroll
        for (int i = 0; i < 4; ++i) {
            uint32_t idx = (hxy[i] ^ hzt[j]) & HASH_MASK;
            float2 f = __half22float2(s_tbl[idx]);
            float w = wxy[i] * wzt[j];
            a0 = fmaf(w, f.x, a0);
            a1 = fmaf(w, f.y, a1);
        }
    }
    return __floats2half2_rn(a0, a1);
}

__global__ void __launch_bounds__(CTA_THREADS)
hash_enc4d_fused_kernel(const float* __restrict__ coords,
                        const float* __restrict__ ts,
                        const float* __restrict__ tables,
                        float* __restrict__ out,
                        ResArr res, int n)
{
    extern __shared__ __half2 s_tbl[];  // 128 KB: table; reused as transpose tile

    const int l     = blockIdx.x;  // level fastest-varying
    const int range = blockIdx.y;

    // ---- load fp32 table slice, convert inline to prescaled half2 ----
    {
        const float4* __restrict__ src = (const float4*)(tables + (size_t)l * HASHMAP_SIZE * 2);
#pragma unroll
        for (int i = threadIdx.x; i < HASHMAP_SIZE / 2; i += CTA_THREADS) {
            float4 v = src[i];
            s_tbl[2 * i + 0] = __floats2half2_rn(v.x * 16384.0f, v.y * 16384.0f);
            s_tbl[2 * i + 1] = __floats2half2_rn(v.z * 16384.0f, v.w * 16384.0f);
        }
    }
    __syncthreads();

    const float rf = (float)res.r[l];
    __half2* __restrict__ sc = g_scr + (size_t)l * n;

    const int base = range * PTS_PER_CTA;
    const int nq_end = min(base + PTS_PER_CTA, n & ~3);

    const float4* __restrict__ c4 = (const float4*)coords;
    const float4* __restrict__ t4 = (const float4*)ts;

    // ---- main: 4 consecutive points per thread, vectorized I/O ----
    for (int p = base + threadIdx.x * 4; p < nq_end; p += CTA_THREADS * 4) {
        int q = p >> 2;
        float4 a = c4[3 * q + 0];   // x0 y0 z0 x1
        float4 b = c4[3 * q + 1];   // y1 z1 x2 y2
        float4 c = c4[3 * q + 2];   // z2 x3 y3 z3
        float4 tt = t4[q];

        float xs[4] = {(a.x + 50.0f) / 100.0f, (a.w + 50.0f) / 100.0f,
                       (b.z + 50.0f) / 100.0f, (c.y + 50.0f) / 100.0f};
        float ys[4] = {(a.y + 50.0f) / 100.0f, (b.x + 50.0f) / 100.0f,
                       (b.w + 50.0f) / 100.0f, (c.z + 50.0f) / 100.0f};
        float zs[4] = {(a.z + 50.0f) / 100.0f, (b.y + 50.0f) / 100.0f,
                       (c.x + 50.0f) / 100.0f, (c.w + 50.0f) / 100.0f};
        float tc[4] = {fminf(fmaxf(tt.x, 0.0f), 1.0f), fminf(fmaxf(tt.y, 0.0f), 1.0f),
                       fminf(fmaxf(tt.z, 0.0f), 1.0f), fminf(fmaxf(tt.w, 0.0f), 1.0f)};

        union { __half2 h[4]; uint4 u; } r;
#pragma unroll
        for (int k = 0; k < 4; ++k)
            r.h[k] = enc_point(xs[k], ys[k], zs[k], tc[k], rf, s_tbl);

        *(uint4*)(sc + p) = r.u;
    }

    // ---- scalar tail (n % 4 points, CTA whose window covers n) ----
    if (base <= (n & ~3) && base + PTS_PER_CTA >= n) {
        for (int p = (n & ~3) + threadIdx.x; p < n; p += CTA_THREADS) {
            float x = (coords[3 * p + 0] + 50.0f) / 100.0f;
            float y = (coords[3 * p + 1] + 50.0f) / 100.0f;
            float z = (coords[3 * p + 2] + 50.0f) / 100.0f;
            float t = fminf(fmaxf(ts[p], 0.0f), 1.0f);
            sc[p] = enc_point(x, y, z, t, rf, s_tbl);
        }
    }

    // ---- last-arriver epilogue: transpose this range once all 16 levels done ----
    __syncthreads();
    __threadfence();               // publish this CTA's scratch writes gpu-wide
    __syncthreads();

    __shared__ int s_last;
    if (threadIdx.x == 0) {
        int prev = atomicAdd(&g_cnt[range], 1);
        int last = (prev == N_LEVELS - 1);
        if (last) {
            g_cnt[range] = 0;      // self-reset for graph replay
            __threadfence();       // acquire: order subsequent reads after all arrivals
        }
        s_last = last;
    }
    __syncthreads();
    if (!s_last) return;

    // reuse table smem as the transpose tile (69632 B <= 131072 B)
    __half2* tile = s_tbl;
    const int r0   = base;
    const int rend = min(base + PTS_PER_CTA, n);
    float4* __restrict__ out4 = (float4*)out;

    for (int tb = r0; tb < rend; tb += TP_PTS) {
#pragma unroll
        for (int ll = 0; ll < N_LEVELS; ++ll) {
            const __half2* __restrict__ scl = g_scr + (size_t)ll * n;
            int p = tb + threadIdx.x;
            tile[threadIdx.x * TP_STRIDE + ll] =
                (p < rend) ? scl[p] : __half2half2(__float2half(0.0f));
        }
        __syncthreads();

#pragma unroll
        for (int k = 0; k < 8; ++k) {
            int idx = threadIdx.x + k * CTA_THREADS;
            int pt = idx >> 3;
            int q  = idx & 7;
            int p  = tb + pt;
            if (p < rend) {
                float2 f0 = __half22float2(tile[pt * TP_STRIDE + 2 * q]);
                float2 f1 = __half22float2(tile[pt * TP_STRIDE + 2 * q + 1]);
                out4[(size_t)p * 8 + q] =
                    make_float4(f0.x * 0x1p-14f, f0.y * 0x1p-14f,
                                f1.x * 0x1p-14f, f1.y * 0x1p-14f);
            }
        }
        __syncthreads();
    }
}

extern "C" void kernel_launch(void* const* d_in, const int* in_sizes, int n_in,
                              void* d_out, int out_size)
{
    const float* coords = (const float*)d_in[0];
    const float* ts     = (const float*)d_in[1];
    const float* tables = (const float*)d_in[2];
    float* out          = (float*)d_out;

    int n = in_sizes[0] / 3;

    ResArr ra;
    for (int l = 0; l < N_LEVELS; ++l) {
        double f = (double)l / 15.0;
        double v = exp(log(16.0) * (1.0 - f) + log(512.0) * f);
        ra.r[l] = (int)v;
    }

    const int smem_main = HASHMAP_SIZE * (int)sizeof(__half2);  // 131072
    static int configured = 0;
    if (!configured) {
        cudaFuncSetAttribute(hash_enc4d_fused_kernel,
                             cudaFuncAttributeMaxDynamicSharedMemorySize, smem_main);
        configured = 1;
    }

    int ranges = (n + PTS_PER_CTA - 1) / PTS_PER_CTA;   // 148 for n=2M
    dim3 grid(N_LEVELS, ranges);
    hash_enc4d_fused_kernel<<<grid, CTA_THREADS, smem_main>>>(coords, ts, tables,
                                                              out, ra, n);
}

// round 16
// speedup vs baseline: 1.3728x; 1.3728x over previous
#include <cuda_runtime.h>
#include <cuda_fp16.h>
#include <math.h>
#include <stdint.h>

#define N_LEVELS 16
#define HASH_MASK 32767u
#define HASHMAP_SIZE 32768
#define PTS_PER_CTA 54272      // 37 ranges * 16 levels = 592 CTAs = 4 waves
#define CTA_THREADS 1024
#define MAX_POINTS 2000000

#define TP_THREADS 1024
#define TP_PTS 1024
#define TP_STRIDE 17           // half2 units; odd -> conflict-free STS

struct ResArr { int r[N_LEVELS]; };

// level-major half2 scratch (carrying the 2^14 prescale): 128 MB
__device__ __align__(256) __half2 g_scr[(size_t)MAX_POINTS * N_LEVELS];

__device__ __forceinline__ __half2 enc_point(float x, float y, float z, float t,
                                             float rf, const __half2* __restrict__ s_tbl)
{
    const uint32_t P1 = 2654435761u, P2 = 805459861u, P3 = 3674653429u;

    float sx = x * rf, sy = y * rf, sz = z * rf, st = t * rf;
    float gxf = floorf(sx), gyf = floorf(sy), gzf = floorf(sz), gtf = floorf(st);
    float fx = sx - gxf, fy = sy - gyf, fz = sz - gzf, ft = st - gtf;

    uint32_t gx = (uint32_t)(int)gxf;
    uint32_t gy = (uint32_t)(int)gyf;
    uint32_t gz = (uint32_t)(int)gzf;
    uint32_t gt = (uint32_t)(int)gtf;

    uint32_t tx0 = gx,      tx1 = gx + 1u;
    uint32_t ty0 = gy * P1, ty1 = ty0 + P1;
    uint32_t tz0 = gz * P2, tz1 = tz0 + P2;
    uint32_t tt0 = gt * P3, tt1 = tt0 + P3;

    uint32_t hxy[4], hzt[4];
    hxy[0] = tx0 ^ ty0; hxy[1] = tx1 ^ ty0;
    hxy[2] = tx0 ^ ty1; hxy[3] = tx1 ^ ty1;
    hzt[0] = tz0 ^ tt0; hzt[1] = tz1 ^ tt0;
    hzt[2] = tz0 ^ tt1; hzt[3] = tz1 ^ tt1;

    float ux = 1.0f - fx, uy = 1.0f - fy, uz = 1.0f - fz, ut = 1.0f - ft;
    float wxy[4], wzt[4];
    wxy[0] = ux * uy; wxy[1] = fx * uy; wxy[2] = ux * fy; wxy[3] = fx * fy;
    wzt[0] = uz * ut; wzt[1] = fz * ut; wzt[2] = uz * ft; wzt[3] = fz * ft;

    // fp16 partial accumulation: 4 partials of 4 terms each (bounded error),
    // HFMA2 consumes the LDS half2 directly -- no per-corner up-convert.
    __half2 acc0 = __float2half2_rn(0.0f);
    __half2 acc1 = acc0, acc2 = acc0, acc3 = acc0;
#pragma unroll
    for (int i = 0; i < 4; ++i) {
        uint32_t i0 = (hxy[i] ^ hzt[0]) & HASH_MASK;
        uint32_t i1 = (hxy[i] ^ hzt[1]) & HASH_MASK;
        uint32_t i2 = (hxy[i] ^ hzt[2]) & HASH_MASK;
        uint32_t i3 = (hxy[i] ^ hzt[3]) & HASH_MASK;
        acc0 = __hfma2(__float2half2_rn(wxy[i] * wzt[0]), s_tbl[i0], acc0);
        acc1 = __hfma2(__float2half2_rn(wxy[i] * wzt[1]), s_tbl[i1], acc1);
        acc2 = __hfma2(__float2half2_rn(wxy[i] * wzt[2]), s_tbl[i2], acc2);
        acc3 = __hfma2(__float2half2_rn(wxy[i] * wzt[3]), s_tbl[i3], acc3);
    }
    float2 s0 = __half22float2(acc0);
    float2 s1 = __half22float2(acc1);
    float2 s2 = __half22float2(acc2);
    float2 s3 = __half22float2(acc3);
    float a0 = (s0.x + s1.x) + (s2.x + s3.x);
    float a1 = (s0.y + s1.y) + (s2.y + s3.y);
    return __floats2half2_rn(a0, a1);
}

__global__ void __launch_bounds__(CTA_THREADS)
hash_enc4d_smem_kernel(const float* __restrict__ coords,
                       const float* __restrict__ ts,
                       const float* __restrict__ tables,
                       ResArr res, int n)
{
    extern __shared__ __half2 s_tbl[];  // 32768 entries = 128 KB

    const int l = blockIdx.x;  // level fastest-varying: co-resident levels share coords in L2

    // Load fp32 table slice, convert inline to prescaled half2.
    {
        const float4* __restrict__ src = (const float4*)(tables + (size_t)l * HASHMAP_SIZE * 2);
#pragma unroll
        for (int i = threadIdx.x; i < HASHMAP_SIZE / 2; i += CTA_THREADS) {
            float4 v = src[i];
            s_tbl[2 * i + 0] = __floats2half2_rn(v.x * 16384.0f, v.y * 16384.0f);
            s_tbl[2 * i + 1] = __floats2half2_rn(v.z * 16384.0f, v.w * 16384.0f);
        }
    }
    __syncthreads();

    const float rf = (float)res.r[l];
    __half2* __restrict__ sc = g_scr + (size_t)l * n;

    const int base = blockIdx.y * PTS_PER_CTA;
    const int nq_end = min(base + PTS_PER_CTA, n & ~3);  // quad-aligned region

    const float4* __restrict__ c4 = (const float4*)coords;
    const float4* __restrict__ t4 = (const float4*)ts;

    // ---- quad path: 4 consecutive points per thread, fully vectorized I/O ----
    for (int p = base + threadIdx.x * 4; p < nq_end; p += CTA_THREADS * 4) {
        int q = p >> 2;
        float4 a = c4[3 * q + 0];   // x0 y0 z0 x1
        float4 b = c4[3 * q + 1];   // y1 z1 x2 y2
        float4 c = c4[3 * q + 2];   // z2 x3 y3 z3
        float4 tt = t4[q];

        float xs[4] = {(a.x + 50.0f) / 100.0f, (a.w + 50.0f) / 100.0f,
                       (b.z + 50.0f) / 100.0f, (c.y + 50.0f) / 100.0f};
        float ys[4] = {(a.y + 50.0f) / 100.0f, (b.x + 50.0f) / 100.0f,
                       (b.w + 50.0f) / 100.0f, (c.z + 50.0f) / 100.0f};
        float zs[4] = {(a.z + 50.0f) / 100.0f, (b.y + 50.0f) / 100.0f,
                       (c.x + 50.0f) / 100.0f, (c.w + 50.0f) / 100.0f};
        float tc[4] = {fminf(fmaxf(tt.x, 0.0f), 1.0f), fminf(fmaxf(tt.y, 0.0f), 1.0f),
                       fminf(fmaxf(tt.z, 0.0f), 1.0f), fminf(fmaxf(tt.w, 0.0f), 1.0f)};

        union { __half2 h[4]; uint4 u; } r;
#pragma unroll
        for (int k = 0; k < 4; ++k)
            r.h[k] = enc_point(xs[k], ys[k], zs[k], tc[k], rf, s_tbl);

        *(uint4*)(sc + p) = r.u;
    }

    // ---- scalar tail (last CTA only, n % 4 points) ----
    if (base + PTS_PER_CTA >= n) {
        for (int p = (n & ~3) + threadIdx.x; p < n; p += CTA_THREADS) {
            float x = (coords[3 * p + 0] + 50.0f) / 100.0f;
            float y = (coords[3 * p + 1] + 50.0f) / 100.0f;
            float z = (coords[3 * p + 2] + 50.0f) / 100.0f;
            float t = fminf(fmaxf(ts[p], 0.0f), 1.0f);
            sc[p] = enc_point(x, y, z, t, rf, s_tbl);
        }
    }
}

// Transpose + descale: g_scr[l][p] (half2, prescaled) -> out[p][...] (fp32).
__global__ void __launch_bounds__(TP_THREADS)
transpose_kernel(float* __restrict__ out, int n)
{
    extern __shared__ __half2 tile[];  // 1024*17*4 = 69632 B

    const int base = blockIdx.x * TP_PTS;
    float4* __restrict__ out4 = (float4*)out;

    if (base + TP_PTS <= n) {
#pragma unroll
        for (int l = 0; l < N_LEVELS; ++l) {
            const __half2* __restrict__ sc = g_scr + (size_t)l * n + base;
            tile[threadIdx.x * TP_STRIDE + l] = sc[threadIdx.x];
        }
        __syncthreads();

#pragma unroll
        for (int k = 0; k < 8; ++k) {
            int idx = threadIdx.x + k * TP_THREADS;
            int pt = idx >> 3;
            int q  = idx & 7;
            float2 f0 = __half22float2(tile[pt * TP_STRIDE + 2 * q]);
            float2 f1 = __half22float2(tile[pt * TP_STRIDE + 2 * q + 1]);
            out4[(size_t)(base + pt) * 8 + q] =
                make_float4(f0.x * 0x1p-14f, f0.y * 0x1p-14f,
                            f1.x * 0x1p-14f, f1.y * 0x1p-14f);
        }
    } else {
#pragma unroll
        for (int l = 0; l < N_LEVELS; ++l) {
            const __half2* __restrict__ sc = g_scr + (size_t)l * n;
            int p = base + threadIdx.x;
            tile[threadIdx.x * TP_STRIDE + l] =
                (p < n) ? sc[p] : __half2half2(__float2half(0.0f));
        }
        __syncthreads();

        for (int k = 0; k < 8; ++k) {
            int idx = threadIdx.x + k * TP_THREADS;
            int pt = idx >> 3;
            int q  = idx & 7;
            int p  = base + pt;
            if (p < n) {
                float2 f0 = __half22float2(tile[pt * TP_STRIDE + 2 * q]);
                float2 f1 = __half22float2(tile[pt * TP_STRIDE + 2 * q + 1]);
                out4[(size_t)p * 8 + q] =
                    make_float4(f0.x * 0x1p-14f, f0.y * 0x1p-14f,
                                f1.x * 0x1p-14f, f1.y * 0x1p-14f);
            }
        }
    }
}

extern "C" void kernel_launch(void* const* d_in, const int* in_sizes, int n_in,
                              void* d_out, int out_size)
{
    const float* coords = (const float*)d_in[0];
    const float* ts     = (const float*)d_in[1];
    const float* tables = (const float*)d_in[2];
    float* out          = (float*)d_out;

    int n = in_sizes[0] / 3;

    ResArr ra;
    for (int l = 0; l < N_LEVELS; ++l) {
        double f = (double)l / 15.0;
        double v = exp(log(16.0) * (1.0 - f) + log(512.0) * f);
        ra.r[l] = (int)v;
    }

    const int smem_main = HASHMAP_SIZE * (int)sizeof(__half2);        // 131072
    const int smem_tp   = TP_PTS * TP_STRIDE * (int)sizeof(__half2);  // 69632
    static int configured = 0;
    if (!configured) {
        cudaFuncSetAttribute(hash_enc4d_smem_kernel,
                             cudaFuncAttributeMaxDynamicSharedMemorySize, smem_main);
        cudaFuncSetAttribute(transpose_kernel,
                             cudaFuncAttributeMaxDynamicSharedMemorySize, smem_tp);
        configured = 1;
    }

    // 1) 4-wave level-fastest encode (4 pts/thread, vectorized coords inline)
    dim3 grid(N_LEVELS, (n + PTS_PER_CTA - 1) / PTS_PER_CTA);
    hash_enc4d_smem_kernel<<<grid, CTA_THREADS, smem_main>>>(coords, ts, tables, ra, n);

    // 2) full-occupancy conflict-free transpose + descale
    int tp_blocks = (n + TP_PTS - 1) / TP_PTS;
    transpose_kernel<<<tp_blocks, TP_THREADS, smem_tp>>>(out, n);
}

// round 17
// speedup vs baseline: 1.3807x; 1.0058x over previous
#include <cuda_runtime.h>
#include <cuda_fp16.h>
#include <math.h>
#include <stdint.h>

#define N_LEVELS 16
#define HASH_MASK 32767u
#define HASHMAP_SIZE 32768
#define PTS_PER_CTA 54272      // 37 ranges * 16 levels = 592 CTAs = 4 waves total
#define CTA_THREADS 1024
#define MAX_POINTS 2000000

#define TP_THREADS 1024
#define TP_PTS 1024
#define TP_STRIDE 17           // half2 units; odd -> conflict-free STS

struct ResArr { int r[N_LEVELS]; };

// level-major half2 scratch (carrying the 2^14 prescale): 128 MB
__device__ __align__(256) __half2 g_scr[(size_t)MAX_POINTS * N_LEVELS];

__device__ __forceinline__ __half2 enc_point(float x, float y, float z, float t,
                                             float rf, const __half2* __restrict__ s_tbl)
{
    const uint32_t P1 = 2654435761u, P2 = 805459861u, P3 = 3674653429u;

    float sx = x * rf, sy = y * rf, sz = z * rf, st = t * rf;
    float gxf = floorf(sx), gyf = floorf(sy), gzf = floorf(sz), gtf = floorf(st);
    float fx = sx - gxf, fy = sy - gyf, fz = sz - gzf, ft = st - gtf;

    uint32_t gx = (uint32_t)(int)gxf;
    uint32_t gy = (uint32_t)(int)gyf;
    uint32_t gz = (uint32_t)(int)gzf;
    uint32_t gt = (uint32_t)(int)gtf;

    uint32_t tx0 = gx,      tx1 = gx + 1u;
    uint32_t ty0 = gy * P1, ty1 = ty0 + P1;
    uint32_t tz0 = gz * P2, tz1 = tz0 + P2;
    uint32_t tt0 = gt * P3, tt1 = tt0 + P3;

    uint32_t hxy[4], hzt[4];
    hxy[0] = tx0 ^ ty0; hxy[1] = tx1 ^ ty0;
    hxy[2] = tx0 ^ ty1; hxy[3] = tx1 ^ ty1;
    hzt[0] = tz0 ^ tt0; hzt[1] = tz1 ^ tt0;
    hzt[2] = tz0 ^ tt1; hzt[3] = tz1 ^ tt1;

    float ux = 1.0f - fx, uy = 1.0f - fy, uz = 1.0f - fz, ut = 1.0f - ft;
    float wxy[4], wzt[4];
    wxy[0] = ux * uy; wxy[1] = fx * uy; wxy[2] = ux * fy; wxy[3] = fx * fy;
    wzt[0] = uz * ut; wzt[1] = fz * ut; wzt[2] = uz * ft; wzt[3] = fz * ft;

    // fp16 partial accumulation: 4 partials of 4 terms each (bounded error),
    // HFMA2 consumes the LDS half2 directly -- no per-corner up-convert.
    __half2 acc0 = __float2half2_rn(0.0f);
    __half2 acc1 = acc0, acc2 = acc0, acc3 = acc0;
#pragma unroll
    for (int i = 0; i < 4; ++i) {
        uint32_t i0 = (hxy[i] ^ hzt[0]) & HASH_MASK;
        uint32_t i1 = (hxy[i] ^ hzt[1]) & HASH_MASK;
        uint32_t i2 = (hxy[i] ^ hzt[2]) & HASH_MASK;
        uint32_t i3 = (hxy[i] ^ hzt[3]) & HASH_MASK;
        acc0 = __hfma2(__float2half2_rn(wxy[i] * wzt[0]), s_tbl[i0], acc0);
        acc1 = __hfma2(__float2half2_rn(wxy[i] * wzt[1]), s_tbl[i1], acc1);
        acc2 = __hfma2(__float2half2_rn(wxy[i] * wzt[2]), s_tbl[i2], acc2);
        acc3 = __hfma2(__float2half2_rn(wxy[i] * wzt[3]), s_tbl[i3], acc3);
    }
    float2 s0 = __half22float2(acc0);
    float2 s1 = __half22float2(acc1);
    float2 s2 = __half22float2(acc2);
    float2 s3 = __half22float2(acc3);
    float a0 = (s0.x + s1.x) + (s2.x + s3.x);
    float a1 = (s0.y + s1.y) + (s2.y + s3.y);
    return __floats2half2_rn(a0, a1);
}

__global__ void __launch_bounds__(CTA_THREADS)
hash_enc4d_smem_kernel(const float* __restrict__ coords,
                       const float* __restrict__ ts,
                       const float* __restrict__ tables,
                       ResArr res, int n, int range0)
{
    extern __shared__ __half2 s_tbl[];  // 32768 entries = 128 KB

    const int l = blockIdx.x;  // level fastest-varying: co-resident levels share coords in L2

    // Load fp32 table slice, convert inline to prescaled half2.
    {
        const float4* __restrict__ src = (const float4*)(tables + (size_t)l * HASHMAP_SIZE * 2);
#pragma unroll
        for (int i = threadIdx.x; i < HASHMAP_SIZE / 2; i += CTA_THREADS) {
            float4 v = src[i];
            s_tbl[2 * i + 0] = __floats2half2_rn(v.x * 16384.0f, v.y * 16384.0f);
            s_tbl[2 * i + 1] = __floats2half2_rn(v.z * 16384.0f, v.w * 16384.0f);
        }
    }
    __syncthreads();

    const float rf = (float)res.r[l];
    __half2* __restrict__ sc = g_scr + (size_t)l * n;

    const int base = (range0 + blockIdx.y) * PTS_PER_CTA;
    const int nq_end = min(base + PTS_PER_CTA, n & ~3);  // quad-aligned region

    const float4* __restrict__ c4 = (const float4*)coords;
    const float4* __restrict__ t4 = (const float4*)ts;

    // ---- quad path: 4 consecutive points per thread, fully vectorized I/O ----
    for (int p = base + threadIdx.x * 4; p < nq_end; p += CTA_THREADS * 4) {
        int q = p >> 2;
        float4 a = c4[3 * q + 0];   // x0 y0 z0 x1
        float4 b = c4[3 * q + 1];   // y1 z1 x2 y2
        float4 c = c4[3 * q + 2];   // z2 x3 y3 z3
        float4 tt = t4[q];

        float xs[4] = {(a.x + 50.0f) / 100.0f, (a.w + 50.0f) / 100.0f,
                       (b.z + 50.0f) / 100.0f, (c.y + 50.0f) / 100.0f};
        float ys[4] = {(a.y + 50.0f) / 100.0f, (b.x + 50.0f) / 100.0f,
                       (b.w + 50.0f) / 100.0f, (c.z + 50.0f) / 100.0f};
        float zs[4] = {(a.z + 50.0f) / 100.0f, (b.y + 50.0f) / 100.0f,
                       (c.x + 50.0f) / 100.0f, (c.w + 50.0f) / 100.0f};
        float tc[4] = {fminf(fmaxf(tt.x, 0.0f), 1.0f), fminf(fmaxf(tt.y, 0.0f), 1.0f),
                       fminf(fmaxf(tt.z, 0.0f), 1.0f), fminf(fmaxf(tt.w, 0.0f), 1.0f)};

        union { __half2 h[4]; uint4 u; } r;
#pragma unroll
        for (int k = 0; k < 4; ++k)
            r.h[k] = enc_point(xs[k], ys[k], zs[k], tc[k], rf, s_tbl);

        *(uint4*)(sc + p) = r.u;
    }

    // ---- scalar tail (CTA whose window covers n, n % 4 points) ----
    if (base <= (n & ~3) && base + PTS_PER_CTA >= n) {
        for (int p = (n & ~3) + threadIdx.x; p < n; p += CTA_THREADS) {
            float x = (coords[3 * p + 0] + 50.0f) / 100.0f;
            float y = (coords[3 * p + 1] + 50.0f) / 100.0f;
            float z = (coords[3 * p + 2] + 50.0f) / 100.0f;
            float t = fminf(fmaxf(ts[p], 0.0f), 1.0f);
            sc[p] = enc_point(x, y, z, t, rf, s_tbl);
        }
    }
}

// Transpose + descale for points [p0, p0 + gridDim.x*TP_PTS) clipped to n.
// Runs right after its chunk's main: scratch reads are L2 hits; output uses
// streaming stores so it doesn't evict the resident scratch.
__global__ void __launch_bounds__(TP_THREADS)
transpose_kernel(float* __restrict__ out, int n, int p0)
{
    extern __shared__ __half2 tile[];  // 1024*17*4 = 69632 B

    const int base = p0 + blockIdx.x * TP_PTS;
    float4* __restrict__ out4 = (float4*)out;

    if (base + TP_PTS <= n) {
#pragma unroll
        for (int l = 0; l < N_LEVELS; ++l) {
            const __half2* __restrict__ sc = g_scr + (size_t)l * n + base;
            tile[threadIdx.x * TP_STRIDE + l] = sc[threadIdx.x];
        }
        __syncthreads();

#pragma unroll
        for (int k = 0; k < 8; ++k) {
            int idx = threadIdx.x + k * TP_THREADS;
            int pt = idx >> 3;
            int q  = idx & 7;
            float2 f0 = __half22float2(tile[pt * TP_STRIDE + 2 * q]);
            float2 f1 = __half22float2(tile[pt * TP_STRIDE + 2 * q + 1]);
            __stcs(&out4[(size_t)(base + pt) * 8 + q],
                   make_float4(f0.x * 0x1p-14f, f0.y * 0x1p-14f,
                               f1.x * 0x1p-14f, f1.y * 0x1p-14f));
        }
    } else {
#pragma unroll
        for (int l = 0; l < N_LEVELS; ++l) {
            const __half2* __restrict__ sc = g_scr + (size_t)l * n;
            int p = base + threadIdx.x;
            tile[threadIdx.x * TP_STRIDE + l] =
                (p < n) ? sc[p] : __half2half2(__float2half(0.0f));
        }
        __syncthreads();

        for (int k = 0; k < 8; ++k) {
            int idx = threadIdx.x + k * TP_THREADS;
            int pt = idx >> 3;
            int q  = idx & 7;
            int p  = base + pt;
            if (p < n) {
                float2 f0 = __half22float2(tile[pt * TP_STRIDE + 2 * q]);
                float2 f1 = __half22float2(tile[pt * TP_STRIDE + 2 * q + 1]);
                __stcs(&out4[(size_t)p * 8 + q],
                       make_float4(f0.x * 0x1p-14f, f0.y * 0x1p-14f,
                                   f1.x * 0x1p-14f, f1.y * 0x1p-14f));
            }
        }
    }
}

extern "C" void kernel_launch(void* const* d_in, const int* in_sizes, int n_in,
                              void* d_out, int out_size)
{
    const float* coords = (const float*)d_in[0];
    const float* ts     = (const float*)d_in[1];
    const float* tables = (const float*)d_in[2];
    float* out          = (float*)d_out;

    int n = in_sizes[0] / 3;

    ResArr ra;
    for (int l = 0; l < N_LEVELS; ++l) {
        double f = (double)l / 15.0;
        double v = exp(log(16.0) * (1.0 - f) + log(512.0) * f);
        ra.r[l] = (int)v;
    }

    const int smem_main = HASHMAP_SIZE * (int)sizeof(__half2);        // 131072
    const int smem_tp   = TP_PTS * TP_STRIDE * (int)sizeof(__half2);  // 69632
    static int configured = 0;
    if (!configured) {
        cudaFuncSetAttribute(hash_enc4d_smem_kernel,
                             cudaFuncAttributeMaxDynamicSharedMemorySize, smem_main);
        cudaFuncSetAttribute(transpose_kernel,
                             cudaFuncAttributeMaxDynamicSharedMemorySize, smem_tp);
        configured = 1;
    }

    const int total_ranges = (n + PTS_PER_CTA - 1) / PTS_PER_CTA;  // 37 for n=2M
    const int half = (total_ranges + 1) / 2;                        // 19 + 18

    for (int c = 0; c < 2; ++c) {
        int range0 = c * half;
        if (range0 >= total_ranges) break;
        int ranges_c = (c == 0) ? half : (total_ranges - half);
        int p0 = range0 * PTS_PER_CTA;
        int pend = min(p0 + ranges_c * PTS_PER_CTA, n);
        if (pend <= p0) break;

        dim3 grid(N_LEVELS, ranges_c);
        hash_enc4d_smem_kernel<<<grid, CTA_THREADS, smem_main>>>(
            coords, ts, tables, ra, n, range0);

        int tp_blocks = (pend - p0 + TP_PTS - 1) / TP_PTS;
        transpose_kernel<<<tp_blocks, TP_THREADS, smem_tp>>>(out, n, p0);
    }
}